// round 1
// baseline (speedup 1.0000x reference)
#include <cuda_runtime.h>
#include <math.h>

#define D_MODEL 512
#define DI      1024
#define BATCH   8
#define SEQ     4096
#define ROWS    (BATCH*SEQ)     // 32768 tokens

// ---------------- scratch (device globals: allocation-free) ----------------
__device__ float g_xnorm[ROWS * D_MODEL];   // 64 MB
__device__ float g_z    [ROWS * DI];        // 128 MB
__device__ float g_uact [ROWS * DI];        // 128 MB (u after conv+silu)
__device__ float g_delta[ROWS * DI];        // 128 MB
__device__ float g_hA   [ROWS * DI];        // 128 MB (also holds raw u from GEMM1)
__device__ float g_hB   [ROWS * DI];        // 128 MB
__device__ float g_g    [ROWS * DI];        // 128 MB ((y_ssm + u*D)*silu(z))

// ---------------- LayerNorm ----------------
__global__ void __launch_bounds__(256) ln_kernel(const float* __restrict__ x,
                                                 const float* __restrict__ gamma,
                                                 const float* __restrict__ beta) {
    int row = blockIdx.x;
    const float* xr = x + (size_t)row * D_MODEL;
    int t = threadIdx.x;
    float v0 = xr[t], v1 = xr[t + 256];
    float s = v0 + v1, sq = v0 * v0 + v1 * v1;
    __shared__ float sh[32], shq[32];
    #pragma unroll
    for (int o = 16; o; o >>= 1) {
        s  += __shfl_down_sync(0xffffffffu, s,  o);
        sq += __shfl_down_sync(0xffffffffu, sq, o);
    }
    int lane = t & 31, w = t >> 5;
    if (lane == 0) { sh[w] = s; shq[w] = sq; }
    __syncthreads();
    if (t == 0) {
        float ts = 0.f, tq = 0.f;
        #pragma unroll
        for (int i = 0; i < 8; i++) { ts += sh[i]; tq += shq[i]; }
        float mu = ts * (1.0f / D_MODEL);
        float var = tq * (1.0f / D_MODEL) - mu * mu;
        sh[0] = mu;
        shq[0] = rsqrtf(var + 1e-5f);
    }
    __syncthreads();
    float mu = sh[0], rs = shq[0];
    float* orow = g_xnorm + (size_t)row * D_MODEL;
    orow[t]       = (v0 - mu) * rs * gamma[t]       + beta[t];
    orow[t + 256] = (v1 - mu) * rs * gamma[t + 256] + beta[t + 256];
}

// ---------------- fp32 SGEMM, 128x128x8 tile, 8x8 per thread ----------------
// MODE 0: A=g_xnorm (K=512), B=W_in (512x2048). cols<1024 -> g_hA (raw u), else -> g_z
// MODE 1: A=g_uact  (K=1024), B=W_dt. epi: min(softplus(acc+b_dt), 0.15) -> g_delta
// MODE 2: A=g_hB    (K=1024), B=W_ssm_out. epi: (acc + uact*Dp)*silu(z) -> g_g
// MODE 3: A=g_g     (K=1024), B=W_out (1024x512). epi: acc + residual -> outp
__device__ __forceinline__ float softplus_clamp(float v) {
    float sp = (v > 15.0f) ? v : log1pf(expf(v));
    return fminf(sp, 0.15f);
}
__device__ __forceinline__ float siluf(float v) {
    return v / (1.0f + expf(-v));
}

template<int MODE, int N, int K>
__global__ void __launch_bounds__(256) sgemm_kernel(const float* __restrict__ Bw,
                                                    const float* __restrict__ p0,
                                                    float* __restrict__ outp) {
    constexpr int BM = 128, BN = 128, BK = 8;
    __shared__ float As[BK][BM];
    __shared__ float Bs[BK][BN];

    const float* A;
    if (MODE == 0)      A = g_xnorm;
    else if (MODE == 1) A = g_uact;
    else if (MODE == 2) A = g_hB;
    else                A = g_g;

    int bx = blockIdx.x;            // N tile
    int by = blockIdx.y;            // M tile
    int tid = threadIdx.x;
    int tx = tid & 15, ty = tid >> 4;

    const float* Ag = A + (size_t)by * BM * K;
    const float* Bg = Bw + bx * BN;

    int arow = tid >> 1, ac4 = (tid & 1) * 4;
    int brow = tid >> 5, bc4 = (tid & 31) * 4;

    float acc[8][8];
    #pragma unroll
    for (int i = 0; i < 8; i++)
        #pragma unroll
        for (int j = 0; j < 8; j++) acc[i][j] = 0.f;

    for (int k0 = 0; k0 < K; k0 += BK) {
        float4 av = *(const float4*)(Ag + (size_t)arow * K + k0 + ac4);
        As[ac4 + 0][arow] = av.x;
        As[ac4 + 1][arow] = av.y;
        As[ac4 + 2][arow] = av.z;
        As[ac4 + 3][arow] = av.w;
        float4 bv = *(const float4*)(Bg + (size_t)(k0 + brow) * N + bc4);
        *(float4*)&Bs[brow][bc4] = bv;
        __syncthreads();
        #pragma unroll
        for (int k = 0; k < BK; k++) {
            float a[8], b[8];
            *(float4*)(a)     = *(const float4*)&As[k][ty * 8];
            *(float4*)(a + 4) = *(const float4*)&As[k][ty * 8 + 4];
            *(float4*)(b)     = *(const float4*)&Bs[k][tx * 8];
            *(float4*)(b + 4) = *(const float4*)&Bs[k][tx * 8 + 4];
            #pragma unroll
            for (int i = 0; i < 8; i++)
                #pragma unroll
                for (int j = 0; j < 8; j++)
                    acc[i][j] = fmaf(a[i], b[j], acc[i][j]);
        }
        __syncthreads();
    }

    int row0 = by * BM + ty * 8;
    int col0 = bx * BN + tx * 8;

    #pragma unroll
    for (int i = 0; i < 8; i++) {
        int row = row0 + i;
        if (MODE == 0) {
            // split into u (raw, into g_hA) and z
            bool is_u = (col0 < DI);
            float* dst = is_u ? (g_hA + (size_t)row * DI + col0)
                              : (g_z  + (size_t)row * DI + (col0 - DI));
            #pragma unroll
            for (int jj = 0; jj < 8; jj += 4) {
                float4 v = make_float4(acc[i][jj], acc[i][jj+1], acc[i][jj+2], acc[i][jj+3]);
                *(float4*)(dst + jj) = v;
            }
        } else if (MODE == 1) {
            float* dst = g_delta + (size_t)row * DI + col0;
            #pragma unroll
            for (int jj = 0; jj < 8; jj += 4) {
                float4 v;
                v.x = softplus_clamp(acc[i][jj]     + p0[col0 + jj]);
                v.y = softplus_clamp(acc[i][jj + 1] + p0[col0 + jj + 1]);
                v.z = softplus_clamp(acc[i][jj + 2] + p0[col0 + jj + 2]);
                v.w = softplus_clamp(acc[i][jj + 3] + p0[col0 + jj + 3]);
                *(float4*)(dst + jj) = v;
            }
        } else if (MODE == 2) {
            size_t o = (size_t)row * DI + col0;
            float* dst = g_g + o;
            #pragma unroll
            for (int jj = 0; jj < 8; jj += 4) {
                float4 uu = *(const float4*)(g_uact + o + jj);
                float4 zz = *(const float4*)(g_z    + o + jj);
                float4 v;
                v.x = (acc[i][jj]     + uu.x * p0[col0 + jj])     * siluf(zz.x);
                v.y = (acc[i][jj + 1] + uu.y * p0[col0 + jj + 1]) * siluf(zz.y);
                v.z = (acc[i][jj + 2] + uu.z * p0[col0 + jj + 2]) * siluf(zz.z);
                v.w = (acc[i][jj + 3] + uu.w * p0[col0 + jj + 3]) * siluf(zz.w);
                *(float4*)(dst + jj) = v;
            }
        } else {
            size_t o = (size_t)row * D_MODEL + col0;
            #pragma unroll
            for (int jj = 0; jj < 8; jj += 4) {
                float4 r = *(const float4*)(p0 + o + jj);
                float4 v = make_float4(acc[i][jj] + r.x, acc[i][jj+1] + r.y,
                                       acc[i][jj+2] + r.z, acc[i][jj+3] + r.w);
                *(float4*)(outp + o + jj) = v;
            }
        }
    }
}

// ---------------- local depthwise conv (zero pad) + bias + SiLU ----------------
__global__ void __launch_bounds__(256) conv_local_kernel(const float* __restrict__ w,
                                                         const float* __restrict__ bias) {
    int idx = blockIdx.x * 256 + threadIdx.x;        // < 2^25, fits int
    int c = idx & (DI - 1);
    int n = (idx >> 10) & (SEQ - 1);
    int b = idx >> 22;
    int y = n >> 6, x = n & 63;
    const float* wc = w + c * 9;
    float acc = bias[c];
    #pragma unroll
    for (int ky = 0; ky < 3; ky++) {
        int yy = y + ky - 1;
        if ((unsigned)yy >= 64u) continue;
        #pragma unroll
        for (int kx = 0; kx < 3; kx++) {
            int xx = x + kx - 1;
            if ((unsigned)xx >= 64u) continue;
            int srow = (b << 12) | (yy << 6) | xx;
            acc = fmaf(wc[ky * 3 + kx], g_hA[(size_t)srow * DI + c], acc);
        }
    }
    g_uact[idx] = siluf(acc);
}

// ---------------- diff conv (replicate pad) + Euler step ----------------
__global__ void __launch_bounds__(256) conv_diff_kernel(const float* __restrict__ hin,
                                                        float* __restrict__ hout,
                                                        const float* __restrict__ w,
                                                        const float* __restrict__ alpha,
                                                        const float* __restrict__ beta) {
    int idx = blockIdx.x * 256 + threadIdx.x;
    int c = idx & (DI - 1);
    int n = (idx >> 10) & (SEQ - 1);
    int b = idx >> 22;
    int y = n >> 6, x = n & 63;
    const float* wc = w + c * 9;
    float acc = 0.f;
    #pragma unroll
    for (int ky = 0; ky < 3; ky++) {
        int yy = min(max(y + ky - 1, 0), 63);
        #pragma unroll
        for (int kx = 0; kx < 3; kx++) {
            int xx = min(max(x + kx - 1, 0), 63);
            int srow = (b << 12) | (yy << 6) | xx;
            acc = fmaf(wc[ky * 3 + kx], hin[(size_t)srow * DI + c], acc);
        }
    }
    float h = hin[idx];
    float d = g_delta[idx];
    hout[idx] = h + 0.25f * (d * acc + alpha[c] * h - beta[c] * h * h * h);
}

// device-symbol accessors for Euler ping-pong (host needs pointers)
__global__ void dummy() {}

extern "C" void kernel_launch(void* const* d_in, const int* in_sizes, int n_in,
                              void* d_out, int out_size) {
    const float* x           = (const float*)d_in[0];
    const float* ln_gamma    = (const float*)d_in[1];
    const float* ln_beta     = (const float*)d_in[2];
    const float* W_in        = (const float*)d_in[3];
    const float* conv_lw     = (const float*)d_in[4];
    const float* conv_lb     = (const float*)d_in[5];
    const float* W_dt        = (const float*)d_in[6];
    const float* b_dt        = (const float*)d_in[7];
    const float* D_param     = (const float*)d_in[8];
    const float* conv_dw     = (const float*)d_in[9];
    const float* alpha       = (const float*)d_in[10];
    const float* beta_r      = (const float*)d_in[11];
    const float* W_ssm_out   = (const float*)d_in[12];
    const float* W_out       = (const float*)d_in[13];
    float* out               = (float*)d_out;

    // resolve scratch symbols once per call (cheap, capture-safe host API)
    float *hA, *hB, *uact;
    cudaGetSymbolAddress((void**)&hA,   g_hA);
    cudaGetSymbolAddress((void**)&hB,   g_hB);
    cudaGetSymbolAddress((void**)&uact, g_uact);

    const int EW_BLOCKS = (ROWS * DI) / 256;

    // 1) LayerNorm
    ln_kernel<<<ROWS, 256>>>(x, ln_gamma, ln_beta);

    // 2) in_proj: xz = x_norm @ W_in  -> raw u (g_hA) and z (g_z)
    sgemm_kernel<0, 2 * DI, D_MODEL><<<dim3(16, ROWS / 128), 256>>>(W_in, nullptr, nullptr);

    // 3) local depthwise conv + bias + SiLU -> g_uact
    conv_local_kernel<<<EW_BLOCKS, 256>>>(conv_lw, conv_lb);

    // 4) delta_d = min(softplus(u @ W_dt + b_dt), 0.15) -> g_delta
    sgemm_kernel<1, DI, DI><<<dim3(8, ROWS / 128), 256>>>(W_dt, b_dt, nullptr);

    // 5) Euler loop, K_steps = 4 (dt = 0.25), ping-pong uact -> hA -> hB -> hA -> hB
    conv_diff_kernel<<<EW_BLOCKS, 256>>>(uact, hA, conv_dw, alpha, beta_r);
    conv_diff_kernel<<<EW_BLOCKS, 256>>>(hA,   hB, conv_dw, alpha, beta_r);
    conv_diff_kernel<<<EW_BLOCKS, 256>>>(hB,   hA, conv_dw, alpha, beta_r);
    conv_diff_kernel<<<EW_BLOCKS, 256>>>(hA,   hB, conv_dw, alpha, beta_r);

    // 6) g = (h @ W_ssm_out + u*D) * silu(z) -> g_g
    sgemm_kernel<2, DI, DI><<<dim3(8, ROWS / 128), 256>>>(W_ssm_out, D_param, nullptr);

    // 7) out = g @ W_out + residual
    sgemm_kernel<3, D_MODEL, DI><<<dim3(4, ROWS / 128), 256>>>(W_out, x, out);
}

// round 3
// speedup vs baseline: 2.1529x; 2.1529x over previous
#include <cuda_runtime.h>
#include <cuda_bf16.h>
#include <math.h>
#include <stdint.h>

#define D_MODEL 512
#define DI      1024
#define ROWS    32768

// ---------------- scratch (device globals) ----------------
__device__ __nv_bfloat16 g_xn_hi[ROWS * D_MODEL];
__device__ __nv_bfloat16 g_xn_lo[ROWS * D_MODEL];
__device__ float g_u    [ROWS * DI];
__device__ float g_z    [ROWS * DI];
__device__ float g_uact [ROWS * DI];
__device__ __nv_bfloat16 g_ua_hi[ROWS * DI];
__device__ __nv_bfloat16 g_ua_lo[ROWS * DI];
__device__ float g_delta[ROWS * DI];
__device__ float g_hA   [ROWS * DI];
__device__ float g_hB   [ROWS * DI];
__device__ __nv_bfloat16 g_h_hi[ROWS * DI];
__device__ __nv_bfloat16 g_h_lo[ROWS * DI];
__device__ __nv_bfloat16 g_g_hi[ROWS * DI];
__device__ __nv_bfloat16 g_g_lo[ROWS * DI];
// transposed + split weights: [N][K] bf16
__device__ __nv_bfloat16 g_win_hi [2048 * 512];
__device__ __nv_bfloat16 g_win_lo [2048 * 512];
__device__ __nv_bfloat16 g_wdt_hi [1024 * 1024];
__device__ __nv_bfloat16 g_wdt_lo [1024 * 1024];
__device__ __nv_bfloat16 g_wssm_hi[1024 * 1024];
__device__ __nv_bfloat16 g_wssm_lo[1024 * 1024];
__device__ __nv_bfloat16 g_wout_hi[512 * 1024];
__device__ __nv_bfloat16 g_wout_lo[512 * 1024];

// ---------------- small helpers ----------------
__device__ __forceinline__ float siluf(float v) { return v / (1.0f + expf(-v)); }
__device__ __forceinline__ float softplus_clamp(float v) {
    float sp = (v > 15.0f) ? v : log1pf(expf(v));
    return fminf(sp, 0.15f);
}
__device__ __forceinline__ void split2(float v, __nv_bfloat16& hi, __nv_bfloat16& lo) {
    hi = __float2bfloat16(v);
    lo = __float2bfloat16(v - __bfloat162float(hi));
}

__device__ __forceinline__ void cpasync16(uint32_t dst, const void* src) {
    asm volatile("cp.async.cg.shared.global [%0], [%1], 16;" :: "r"(dst), "l"(src));
}
__device__ __forceinline__ void ldsm4(uint32_t a, uint32_t& r0, uint32_t& r1,
                                      uint32_t& r2, uint32_t& r3) {
    asm volatile("ldmatrix.sync.aligned.m8n8.x4.shared.b16 {%0,%1,%2,%3}, [%4];"
                 : "=r"(r0), "=r"(r1), "=r"(r2), "=r"(r3) : "r"(a));
}
__device__ __forceinline__ void mma16816(float* c, uint32_t a0, uint32_t a1,
                                         uint32_t a2, uint32_t a3,
                                         uint32_t b0, uint32_t b1) {
    asm volatile(
        "mma.sync.aligned.m16n8k16.row.col.f32.bf16.bf16.f32 "
        "{%0,%1,%2,%3}, {%4,%5,%6,%7}, {%8,%9}, {%0,%1,%2,%3};"
        : "+f"(c[0]), "+f"(c[1]), "+f"(c[2]), "+f"(c[3])
        : "r"(a0), "r"(a1), "r"(a2), "r"(a3), "r"(b0), "r"(b1));
}

// ---------------- LayerNorm -> bf16 hi/lo split ----------------
__global__ void __launch_bounds__(256) ln_kernel(const float* __restrict__ x,
                                                 const float* __restrict__ gamma,
                                                 const float* __restrict__ beta) {
    int row = blockIdx.x;
    const float* xr = x + (size_t)row * D_MODEL;
    int t = threadIdx.x;
    float v0 = xr[t], v1 = xr[t + 256];
    float s = v0 + v1, sq = v0 * v0 + v1 * v1;
    __shared__ float sh[32], shq[32];
    #pragma unroll
    for (int o = 16; o; o >>= 1) {
        s  += __shfl_down_sync(0xffffffffu, s,  o);
        sq += __shfl_down_sync(0xffffffffu, sq, o);
    }
    int lane = t & 31, w = t >> 5;
    if (lane == 0) { sh[w] = s; shq[w] = sq; }
    __syncthreads();
    if (t == 0) {
        float ts = 0.f, tq = 0.f;
        #pragma unroll
        for (int i = 0; i < 8; i++) { ts += sh[i]; tq += shq[i]; }
        float mu = ts * (1.0f / D_MODEL);
        float var = tq * (1.0f / D_MODEL) - mu * mu;
        sh[0] = mu;
        shq[0] = rsqrtf(var + 1e-5f);
    }
    __syncthreads();
    float mu = sh[0], rs = shq[0];
    size_t o = (size_t)row * D_MODEL;
    float a = (v0 - mu) * rs * gamma[t] + beta[t];
    float b = (v1 - mu) * rs * gamma[t + 256] + beta[t + 256];
    __nv_bfloat16 hi, lo;
    split2(a, hi, lo); g_xn_hi[o + t] = hi;       g_xn_lo[o + t] = lo;
    split2(b, hi, lo); g_xn_hi[o + t + 256] = hi; g_xn_lo[o + t + 256] = lo;
}

// ---------------- weight transpose + split: W[K][N] -> T[N][K] bf16 hi/lo ----------------
__global__ void __launch_bounds__(256) wprep_kernel(const float* __restrict__ W,
                                                    __nv_bfloat16* __restrict__ Thi,
                                                    __nv_bfloat16* __restrict__ Tlo,
                                                    int K, int N) {
    __shared__ float t[32][33];
    int n0 = blockIdx.x * 32, k0 = blockIdx.y * 32;
    int tx = threadIdx.x & 31, ty = threadIdx.x >> 5;  // 32x8
    #pragma unroll
    for (int dy = 0; dy < 32; dy += 8)
        t[ty + dy][tx] = W[(size_t)(k0 + ty + dy) * N + n0 + tx];
    __syncthreads();
    #pragma unroll
    for (int dy = 0; dy < 32; dy += 8) {
        float v = t[tx][ty + dy];
        __nv_bfloat16 hi, lo;
        split2(v, hi, lo);
        size_t o = (size_t)(n0 + ty + dy) * K + k0 + tx;
        Thi[o] = hi;
        Tlo[o] = lo;
    }
}

// ---------------- HMMA split-bf16 GEMM ----------------
// A: [M][K] bf16 hi/lo (row-major), B: [N][K] bf16 hi/lo (row-major, i.e. W^T)
// tile 128x128x32, 256 threads, 8 warps (4m x 2n), warp tile 32m x 64n
// smem row stride = 40 bf16 (80B) -> conflict-free ldmatrix
// MODE 0: -> g_u / g_z split at col 1024
// MODE 1: delta = min(softplus(acc+b_dt),0.15) -> g_delta
// MODE 2: g = (acc + uact*Dp)*silu(z) -> g_g_hi/lo
// MODE 3: out = acc + residual
#define ASZ 10240u          // one 128x40 bf16 tile in bytes
#define STG 40960u          // 4 tiles per stage

template<int K, bool SPLIT3>
__device__ __forceinline__ void load_stage(uint32_t st, int tid,
        const __nv_bfloat16* __restrict__ Ahi, const __nv_bfloat16* __restrict__ Alo,
        const __nv_bfloat16* __restrict__ Bhi, const __nv_bfloat16* __restrict__ Blo,
        size_t arow, size_t brow, int chunk) {
    #pragma unroll
    for (int i = 0; i < 2; i++) {
        int idx = tid + i * 256;
        int r = idx >> 2, cb = (idx & 3) * 16;
        uint32_t sa = st + (uint32_t)(r * 80 + cb);
        size_t ga = (arow + r) * (size_t)(K * 2) + chunk * 64 + cb;
        size_t gb = (brow + r) * (size_t)(K * 2) + chunk * 64 + cb;
        cpasync16(sa,            (const char*)Ahi + ga);
        cpasync16(sa + 2 * ASZ,  (const char*)Bhi + gb);
        if (SPLIT3) {
            cpasync16(sa + ASZ,     (const char*)Alo + ga);
            cpasync16(sa + 3 * ASZ, (const char*)Blo + gb);
        }
    }
    asm volatile("cp.async.commit_group;");
}

template<int MODE, int NOUT, int K, bool SPLIT3>
__global__ void __launch_bounds__(256)
hmma_gemm(const __nv_bfloat16* __restrict__ Ahi, const __nv_bfloat16* __restrict__ Alo,
          const __nv_bfloat16* __restrict__ Bhi, const __nv_bfloat16* __restrict__ Blo,
          const float* __restrict__ p0, const float* __restrict__ res,
          float* __restrict__ outp) {
    extern __shared__ char smem_raw[];
    uint32_t sb = (uint32_t)__cvta_generic_to_shared(smem_raw);
    const int tid = threadIdx.x;
    const int lane = tid & 31, wid = tid >> 5;
    const int wm = wid & 3, wn = wid >> 2;
    const int bx = blockIdx.x, by = blockIdx.y;
    const size_t arow = (size_t)by * 128;
    const size_t brow = (size_t)bx * 128;
    constexpr int NC = K / 32;

    // per-lane ldmatrix offsets
    const int a_r = (lane & 7) + ((lane >> 3) & 1) * 8;
    const int a_c = ((lane >> 4) & 1) * 8;
    const int b_r = (lane & 7) + ((lane >> 4) & 1) * 8;
    const int b_c = ((lane >> 3) & 1) * 8;
    const uint32_t a_off = (uint32_t)((wm * 32 + a_r) * 80 + a_c * 2);
    const uint32_t b_off = 2 * ASZ + (uint32_t)((wn * 64 + b_r) * 80 + b_c * 2);

    load_stage<K, SPLIT3>(sb,       tid, Ahi, Alo, Bhi, Blo, arow, brow, 0);
    load_stage<K, SPLIT3>(sb + STG, tid, Ahi, Alo, Bhi, Blo, arow, brow, 1);

    float acc[2][8][4];
    #pragma unroll
    for (int i = 0; i < 2; i++)
        #pragma unroll
        for (int j = 0; j < 8; j++)
            #pragma unroll
            for (int q = 0; q < 4; q++) acc[i][j][q] = 0.f;

    #pragma unroll 1
    for (int i = 0; i < NC; i++) {
        if (i + 1 < NC) asm volatile("cp.async.wait_group 1;");
        else            asm volatile("cp.async.wait_group 0;");
        __syncthreads();
        uint32_t st = sb + (uint32_t)(i & 1) * STG;
        #pragma unroll
        for (int ks = 0; ks < 2; ks++) {
            uint32_t kb = (uint32_t)(ks * 32);
            uint32_t ah[2][4], al[2][4], bh[4][4], bl[4][4];
            #pragma unroll
            for (int mt = 0; mt < 2; mt++) {
                uint32_t a = st + a_off + (uint32_t)(mt * 16 * 80) + kb;
                ldsm4(a, ah[mt][0], ah[mt][1], ah[mt][2], ah[mt][3]);
                if (SPLIT3) ldsm4(a + ASZ, al[mt][0], al[mt][1], al[mt][2], al[mt][3]);
            }
            #pragma unroll
            for (int np = 0; np < 4; np++) {
                uint32_t b = st + b_off + (uint32_t)(np * 16 * 80) + kb;
                ldsm4(b, bh[np][0], bh[np][1], bh[np][2], bh[np][3]);
                if (SPLIT3) ldsm4(b + ASZ, bl[np][0], bl[np][1], bl[np][2], bl[np][3]);
            }
            #pragma unroll
            for (int mt = 0; mt < 2; mt++)
                #pragma unroll
                for (int nt = 0; nt < 8; nt++) {
                    float* c = acc[mt][nt];
                    int gq = nt >> 1, h = (nt & 1) << 1;
                    mma16816(c, ah[mt][0], ah[mt][1], ah[mt][2], ah[mt][3],
                             bh[gq][h], bh[gq][h + 1]);
                    if (SPLIT3) {
                        mma16816(c, ah[mt][0], ah[mt][1], ah[mt][2], ah[mt][3],
                                 bl[gq][h], bl[gq][h + 1]);
                        mma16816(c, al[mt][0], al[mt][1], al[mt][2], al[mt][3],
                                 bh[gq][h], bh[gq][h + 1]);
                    }
                }
        }
        __syncthreads();
        if (i + 2 < NC)
            load_stage<K, SPLIT3>(st, tid, Ahi, Alo, Bhi, Blo, arow, brow, i + 2);
    }

    // ---- epilogue ----
    const int quad = lane >> 2, qi = lane & 3;
    #pragma unroll
    for (int mt = 0; mt < 2; mt++) {
        #pragma unroll
        for (int nt = 0; nt < 8; nt++) {
            int r0 = by * 128 + wm * 32 + mt * 16 + quad;
            int c  = bx * 128 + wn * 64 + nt * 8 + qi * 2;
            float* a = acc[mt][nt];
            #pragma unroll
            for (int half = 0; half < 2; half++) {
                int row = r0 + half * 8;
                float v0 = a[half * 2], v1 = a[half * 2 + 1];
                if (MODE == 0) {
                    float* dst = (c < DI) ? (g_u + (size_t)row * DI + c)
                                          : (g_z + (size_t)row * DI + (c - DI));
                    *(float2*)dst = make_float2(v0, v1);
                } else if (MODE == 1) {
                    float2 bb = *(const float2*)(p0 + c);
                    float2 o = make_float2(softplus_clamp(v0 + bb.x),
                                           softplus_clamp(v1 + bb.y));
                    *(float2*)(g_delta + (size_t)row * DI + c) = o;
                } else if (MODE == 2) {
                    size_t o = (size_t)row * DI + c;
                    float2 uu = *(const float2*)(g_uact + o);
                    float2 zz = *(const float2*)(g_z + o);
                    float2 dp = *(const float2*)(p0 + c);
                    float w0 = (v0 + uu.x * dp.x) * siluf(zz.x);
                    float w1 = (v1 + uu.y * dp.y) * siluf(zz.y);
                    __nv_bfloat16 h0, l0, h1, l1;
                    split2(w0, h0, l0);
                    split2(w1, h1, l1);
                    *(__nv_bfloat162*)(g_g_hi + o) = __nv_bfloat162(h0, h1);
                    *(__nv_bfloat162*)(g_g_lo + o) = __nv_bfloat162(l0, l1);
                } else {
                    size_t o = (size_t)row * (size_t)NOUT + c;
                    float2 rr = *(const float2*)(res + o);
                    *(float2*)(outp + o) = make_float2(v0 + rr.x, v1 + rr.y);
                }
            }
        }
    }
}

// ---------------- local depthwise conv (zero pad) + bias + SiLU ----------------
__global__ void __launch_bounds__(256) conv_local_kernel(const float* __restrict__ w,
                                                         const float* __restrict__ bias) {
    int idx = blockIdx.x * 256 + threadIdx.x;
    int c = idx & (DI - 1);
    int n = (idx >> 10) & 4095;
    int b = idx >> 22;
    int y = n >> 6, x = n & 63;
    const float* wc = w + c * 9;
    float acc = bias[c];
    #pragma unroll
    for (int ky = 0; ky < 3; ky++) {
        int yy = y + ky - 1;
        if ((unsigned)yy >= 64u) continue;
        #pragma unroll
        for (int kx = 0; kx < 3; kx++) {
            int xx = x + kx - 1;
            if ((unsigned)xx >= 64u) continue;
            int srow = (b << 12) | (yy << 6) | xx;
            acc = fmaf(wc[ky * 3 + kx], g_u[(size_t)srow * DI + c], acc);
        }
    }
    float v = siluf(acc);
    g_uact[idx] = v;
    __nv_bfloat16 hi, lo;
    split2(v, hi, lo);
    g_ua_hi[idx] = hi;
    g_ua_lo[idx] = lo;
}

// ---------------- diff conv (replicate pad) + Euler step ----------------
template<bool LAST>
__global__ void __launch_bounds__(256) conv_diff_kernel(const float* __restrict__ hin,
                                                        float* __restrict__ hout,
                                                        const float* __restrict__ w,
                                                        const float* __restrict__ alpha,
                                                        const float* __restrict__ beta) {
    int idx = blockIdx.x * 256 + threadIdx.x;
    int c = idx & (DI - 1);
    int n = (idx >> 10) & 4095;
    int b = idx >> 22;
    int y = n >> 6, x = n & 63;
    const float* wc = w + c * 9;
    float acc = 0.f;
    #pragma unroll
    for (int ky = 0; ky < 3; ky++) {
        int yy = min(max(y + ky - 1, 0), 63);
        #pragma unroll
        for (int kx = 0; kx < 3; kx++) {
            int xx = min(max(x + kx - 1, 0), 63);
            int srow = (b << 12) | (yy << 6) | xx;
            acc = fmaf(wc[ky * 3 + kx], hin[(size_t)srow * DI + c], acc);
        }
    }
    float h = hin[idx];
    float d = g_delta[idx];
    float v = h + 0.25f * (d * acc + alpha[c] * h - beta[c] * h * h * h);
    if (LAST) {
        __nv_bfloat16 hi, lo;
        split2(v, hi, lo);
        g_h_hi[idx] = hi;
        g_h_lo[idx] = lo;
    } else {
        hout[idx] = v;
    }
}

extern "C" void kernel_launch(void* const* d_in, const int* in_sizes, int n_in,
                              void* d_out, int out_size) {
    const float* x         = (const float*)d_in[0];
    const float* ln_gamma  = (const float*)d_in[1];
    const float* ln_beta   = (const float*)d_in[2];
    const float* W_in      = (const float*)d_in[3];
    const float* conv_lw   = (const float*)d_in[4];
    const float* conv_lb   = (const float*)d_in[5];
    const float* W_dt      = (const float*)d_in[6];
    const float* b_dt      = (const float*)d_in[7];
    const float* D_param   = (const float*)d_in[8];
    const float* conv_dw   = (const float*)d_in[9];
    const float* alpha     = (const float*)d_in[10];
    const float* beta_r    = (const float*)d_in[11];
    const float* W_ssm_out = (const float*)d_in[12];
    const float* W_out     = (const float*)d_in[13];
    float* out             = (float*)d_out;

    __nv_bfloat16 *xn_hi, *xn_lo, *ua_hi, *ua_lo, *h_hi, *h_lo, *gg_hi, *gg_lo;
    __nv_bfloat16 *win_hi, *win_lo, *wdt_hi, *wdt_lo, *wssm_hi, *wssm_lo, *wout_hi, *wout_lo;
    float *hA, *hB, *uact;
    cudaGetSymbolAddress((void**)&xn_hi, g_xn_hi);
    cudaGetSymbolAddress((void**)&xn_lo, g_xn_lo);
    cudaGetSymbolAddress((void**)&ua_hi, g_ua_hi);
    cudaGetSymbolAddress((void**)&ua_lo, g_ua_lo);
    cudaGetSymbolAddress((void**)&h_hi,  g_h_hi);
    cudaGetSymbolAddress((void**)&h_lo,  g_h_lo);
    cudaGetSymbolAddress((void**)&gg_hi, g_g_hi);
    cudaGetSymbolAddress((void**)&gg_lo, g_g_lo);
    cudaGetSymbolAddress((void**)&win_hi,  g_win_hi);
    cudaGetSymbolAddress((void**)&win_lo,  g_win_lo);
    cudaGetSymbolAddress((void**)&wdt_hi,  g_wdt_hi);
    cudaGetSymbolAddress((void**)&wdt_lo,  g_wdt_lo);
    cudaGetSymbolAddress((void**)&wssm_hi, g_wssm_hi);
    cudaGetSymbolAddress((void**)&wssm_lo, g_wssm_lo);
    cudaGetSymbolAddress((void**)&wout_hi, g_wout_hi);
    cudaGetSymbolAddress((void**)&wout_lo, g_wout_lo);
    cudaGetSymbolAddress((void**)&hA,   g_hA);
    cudaGetSymbolAddress((void**)&hB,   g_hB);
    cudaGetSymbolAddress((void**)&uact, g_uact);

    const int SMEM_BYTES = 2 * STG;  // 81920
    cudaFuncSetAttribute((const void*)hmma_gemm<0, 2048, 512,  true>,
                         cudaFuncAttributeMaxDynamicSharedMemorySize, SMEM_BYTES);
    cudaFuncSetAttribute((const void*)hmma_gemm<1, 1024, 1024, false>,
                         cudaFuncAttributeMaxDynamicSharedMemorySize, SMEM_BYTES);
    cudaFuncSetAttribute((const void*)hmma_gemm<2, 1024, 1024, true>,
                         cudaFuncAttributeMaxDynamicSharedMemorySize, SMEM_BYTES);
    cudaFuncSetAttribute((const void*)hmma_gemm<3, 512,  1024, true>,
                         cudaFuncAttributeMaxDynamicSharedMemorySize, SMEM_BYTES);

    const int EW_BLOCKS = (ROWS * DI) / 256;

    // 0) weight transpose + split
    wprep_kernel<<<dim3(2048 / 32, 512 / 32),  256>>>(W_in,      win_hi,  win_lo,  512,  2048);
    wprep_kernel<<<dim3(1024 / 32, 1024 / 32), 256>>>(W_dt,      wdt_hi,  wdt_lo,  1024, 1024);
    wprep_kernel<<<dim3(1024 / 32, 1024 / 32), 256>>>(W_ssm_out, wssm_hi, wssm_lo, 1024, 1024);
    wprep_kernel<<<dim3(512 / 32,  1024 / 32), 256>>>(W_out,     wout_hi, wout_lo, 1024, 512);

    // 1) LayerNorm -> xn hi/lo
    ln_kernel<<<ROWS, 256>>>(x, ln_gamma, ln_beta);

    // 2) in_proj -> u (g_u) and z (g_z)
    hmma_gemm<0, 2048, 512, true><<<dim3(16, ROWS / 128), 256, SMEM_BYTES>>>(
        xn_hi, xn_lo, win_hi, win_lo, nullptr, nullptr, nullptr);

    // 3) local conv + SiLU -> uact (fp32 + hi/lo)
    conv_local_kernel<<<EW_BLOCKS, 256>>>(conv_lw, conv_lb);

    // 4) delta (hi-only: output passes through softplus around -2.25, low precision need)
    hmma_gemm<1, 1024, 1024, false><<<dim3(8, ROWS / 128), 256, SMEM_BYTES>>>(
        ua_hi, ua_lo, wdt_hi, wdt_lo, b_dt, nullptr, nullptr);

    // 5) Euler x4 (last writes h hi/lo)
    conv_diff_kernel<false><<<EW_BLOCKS, 256>>>(uact, hA, conv_dw, alpha, beta_r);
    conv_diff_kernel<false><<<EW_BLOCKS, 256>>>(hA,   hB, conv_dw, alpha, beta_r);
    conv_diff_kernel<false><<<EW_BLOCKS, 256>>>(hB,   hA, conv_dw, alpha, beta_r);
    conv_diff_kernel<true ><<<EW_BLOCKS, 256>>>(hA, nullptr, conv_dw, alpha, beta_r);

    // 6) g = (h@Wssm + u*D) * silu(z) -> g hi/lo
    hmma_gemm<2, 1024, 1024, true><<<dim3(8, ROWS / 128), 256, SMEM_BYTES>>>(
        h_hi, h_lo, wssm_hi, wssm_lo, D_param, nullptr, nullptr);

    // 7) out = g@Wout + residual
    hmma_gemm<3, 512, 1024, true><<<dim3(4, ROWS / 128), 256, SMEM_BYTES>>>(
        gg_hi, gg_lo, wout_hi, wout_lo, nullptr, x, out);
}

// round 4
// speedup vs baseline: 2.2227x; 1.0324x over previous
#include <cuda_runtime.h>
#include <cuda_bf16.h>
#include <math.h>
#include <stdint.h>

#define D_MODEL 512
#define DI      1024
#define ROWS    32768

// ---------------- scratch (device globals) ----------------
__device__ __nv_bfloat16 g_xn_hi[ROWS * D_MODEL];
__device__ __nv_bfloat16 g_xn_lo[ROWS * D_MODEL];
__device__ float g_u    [ROWS * DI];
__device__ float g_z    [ROWS * DI];
__device__ float g_uact [ROWS * DI];
__device__ __nv_bfloat16 g_ua_hi[ROWS * DI];
__device__ __nv_bfloat16 g_ua_lo[ROWS * DI];
__device__ float g_delta[ROWS * DI];
__device__ float g_hA   [ROWS * DI];
__device__ float g_hB   [ROWS * DI];
__device__ __nv_bfloat16 g_h_hi[ROWS * DI];
__device__ __nv_bfloat16 g_h_lo[ROWS * DI];
__device__ __nv_bfloat16 g_g_hi[ROWS * DI];
__device__ __nv_bfloat16 g_g_lo[ROWS * DI];
// transposed + split weights: [N][K] bf16
__device__ __nv_bfloat16 g_win_hi [2048 * 512];
__device__ __nv_bfloat16 g_win_lo [2048 * 512];
__device__ __nv_bfloat16 g_wdt_hi [1024 * 1024];
__device__ __nv_bfloat16 g_wdt_lo [1024 * 1024];
__device__ __nv_bfloat16 g_wssm_hi[1024 * 1024];
__device__ __nv_bfloat16 g_wssm_lo[1024 * 1024];
__device__ __nv_bfloat16 g_wout_hi[512 * 1024];
__device__ __nv_bfloat16 g_wout_lo[512 * 1024];

// ---------------- small helpers ----------------
__device__ __forceinline__ float siluf(float v) { return v / (1.0f + expf(-v)); }
__device__ __forceinline__ float softplus_clamp(float v) {
    float sp = (v > 15.0f) ? v : log1pf(expf(v));
    return fminf(sp, 0.15f);
}
__device__ __forceinline__ void split2(float v, __nv_bfloat16& hi, __nv_bfloat16& lo) {
    hi = __float2bfloat16(v);
    lo = __float2bfloat16(v - __bfloat162float(hi));
}

__device__ __forceinline__ void cpasync16(uint32_t dst, const void* src) {
    asm volatile("cp.async.cg.shared.global [%0], [%1], 16;" :: "r"(dst), "l"(src));
}
__device__ __forceinline__ void ldsm4(uint32_t a, uint32_t& r0, uint32_t& r1,
                                      uint32_t& r2, uint32_t& r3) {
    asm volatile("ldmatrix.sync.aligned.m8n8.x4.shared.b16 {%0,%1,%2,%3}, [%4];"
                 : "=r"(r0), "=r"(r1), "=r"(r2), "=r"(r3) : "r"(a));
}
__device__ __forceinline__ void mma16816(float* c, const uint32_t* a,
                                         uint32_t b0, uint32_t b1) {
    asm volatile(
        "mma.sync.aligned.m16n8k16.row.col.f32.bf16.bf16.f32 "
        "{%0,%1,%2,%3}, {%4,%5,%6,%7}, {%8,%9}, {%0,%1,%2,%3};"
        : "+f"(c[0]), "+f"(c[1]), "+f"(c[2]), "+f"(c[3])
        : "r"(a[0]), "r"(a[1]), "r"(a[2]), "r"(a[3]), "r"(b0), "r"(b1));
}

// ---------------- LayerNorm -> bf16 hi/lo split ----------------
__global__ void __launch_bounds__(256) ln_kernel(const float* __restrict__ x,
                                                 const float* __restrict__ gamma,
                                                 const float* __restrict__ beta) {
    int row = blockIdx.x;
    const float* xr = x + (size_t)row * D_MODEL;
    int t = threadIdx.x;
    float v0 = xr[t], v1 = xr[t + 256];
    float s = v0 + v1, sq = v0 * v0 + v1 * v1;
    __shared__ float sh[32], shq[32];
    #pragma unroll
    for (int o = 16; o; o >>= 1) {
        s  += __shfl_down_sync(0xffffffffu, s,  o);
        sq += __shfl_down_sync(0xffffffffu, sq, o);
    }
    int lane = t & 31, w = t >> 5;
    if (lane == 0) { sh[w] = s; shq[w] = sq; }
    __syncthreads();
    if (t == 0) {
        float ts = 0.f, tq = 0.f;
        #pragma unroll
        for (int i = 0; i < 8; i++) { ts += sh[i]; tq += shq[i]; }
        float mu = ts * (1.0f / D_MODEL);
        float var = tq * (1.0f / D_MODEL) - mu * mu;
        sh[0] = mu;
        shq[0] = rsqrtf(var + 1e-5f);
    }
    __syncthreads();
    float mu = sh[0], rs = shq[0];
    size_t o = (size_t)row * D_MODEL;
    float a = (v0 - mu) * rs * gamma[t] + beta[t];
    float b = (v1 - mu) * rs * gamma[t + 256] + beta[t + 256];
    __nv_bfloat16 hi, lo;
    split2(a, hi, lo); g_xn_hi[o + t] = hi;       g_xn_lo[o + t] = lo;
    split2(b, hi, lo); g_xn_hi[o + t + 256] = hi; g_xn_lo[o + t + 256] = lo;
}

// ---------------- weight transpose + split ----------------
__global__ void __launch_bounds__(256) wprep_kernel(const float* __restrict__ W,
                                                    __nv_bfloat16* __restrict__ Thi,
                                                    __nv_bfloat16* __restrict__ Tlo,
                                                    int K, int N) {
    __shared__ float t[32][33];
    int n0 = blockIdx.x * 32, k0 = blockIdx.y * 32;
    int tx = threadIdx.x & 31, ty = threadIdx.x >> 5;
    #pragma unroll
    for (int dy = 0; dy < 32; dy += 8)
        t[ty + dy][tx] = W[(size_t)(k0 + ty + dy) * N + n0 + tx];
    __syncthreads();
    #pragma unroll
    for (int dy = 0; dy < 32; dy += 8) {
        float v = t[tx][ty + dy];
        __nv_bfloat16 hi, lo;
        split2(v, hi, lo);
        size_t o = (size_t)(n0 + ty + dy) * K + k0 + tx;
        Thi[o] = hi;
        Tlo[o] = lo;
    }
}

// ---------------- HMMA split-bf16 GEMM, 128x256x32 tiles, 3-stage ----------------
// smem per stage: Ahi(10240) Alo(10240) Bhi(20480) Blo(20480) = 61440 B
#define A_SZ   10240u
#define B_OFF  20480u
#define B_SZ   20480u
#define STGSZ  61440u
#define NSTG   3

template<int K, bool SPLIT3>
__device__ __forceinline__ void load_stage(uint32_t st, int tid,
        const __nv_bfloat16* __restrict__ Ahi, const __nv_bfloat16* __restrict__ Alo,
        const __nv_bfloat16* __restrict__ Bhi, const __nv_bfloat16* __restrict__ Blo,
        size_t arow, size_t brow, int chunk) {
    // A: 128 rows x 64B  (512 x 16B ops -> 2/thread)
    #pragma unroll
    for (int i = 0; i < 2; i++) {
        int idx = tid + i * 256;
        int r = idx >> 2, cb = (idx & 3) * 16;
        uint32_t sa = st + (uint32_t)(r * 80 + cb);
        size_t ga = (arow + r) * (size_t)(K * 2) + chunk * 64 + cb;
        cpasync16(sa, (const char*)Ahi + ga);
        if (SPLIT3) cpasync16(sa + A_SZ, (const char*)Alo + ga);
    }
    // B: 256 rows x 64B (1024 x 16B ops -> 4/thread)
    #pragma unroll
    for (int i = 0; i < 4; i++) {
        int idx = tid + i * 256;
        int r = idx >> 2, cb = (idx & 3) * 16;
        uint32_t sbm = st + B_OFF + (uint32_t)(r * 80 + cb);
        size_t gb = (brow + r) * (size_t)(K * 2) + chunk * 64 + cb;
        cpasync16(sbm, (const char*)Bhi + gb);
        if (SPLIT3) cpasync16(sbm + B_SZ, (const char*)Blo + gb);
    }
    asm volatile("cp.async.commit_group;");
}

template<int MODE, int NOUT, int K, bool SPLIT3>
__global__ void __launch_bounds__(256, 1)
hmma_gemm(const __nv_bfloat16* __restrict__ Ahi, const __nv_bfloat16* __restrict__ Alo,
          const __nv_bfloat16* __restrict__ Bhi, const __nv_bfloat16* __restrict__ Blo,
          const float* __restrict__ p0, const float* __restrict__ res,
          float* __restrict__ outp) {
    extern __shared__ char smem_raw[];
    uint32_t sb = (uint32_t)__cvta_generic_to_shared(smem_raw);
    const int tid = threadIdx.x;
    const int lane = tid & 31, wid = tid >> 5;
    const int wm = wid & 3, wn = wid >> 2;           // 4m x 2n, warp tile 32x128
    const int bx = blockIdx.x, by = blockIdx.y;
    const size_t arow = (size_t)by * 128;
    const size_t brow = (size_t)bx * 256;
    constexpr int NC = K / 32;

    const int a_r = (lane & 7) + ((lane >> 3) & 1) * 8;
    const int a_c = ((lane >> 4) & 1) * 8;
    const int b_r = (lane & 7) + ((lane >> 4) & 1) * 8;
    const int b_c = ((lane >> 3) & 1) * 8;
    const uint32_t a_off = (uint32_t)((wm * 32 + a_r) * 80 + a_c * 2);
    const uint32_t b_off = B_OFF + (uint32_t)((wn * 128 + b_r) * 80 + b_c * 2);

    load_stage<K, SPLIT3>(sb,             tid, Ahi, Alo, Bhi, Blo, arow, brow, 0);
    load_stage<K, SPLIT3>(sb + STGSZ,     tid, Ahi, Alo, Bhi, Blo, arow, brow, 1);

    float acc[2][16][4];
    #pragma unroll
    for (int i = 0; i < 2; i++)
        #pragma unroll
        for (int j = 0; j < 16; j++)
            #pragma unroll
            for (int q = 0; q < 4; q++) acc[i][j][q] = 0.f;

    #pragma unroll 1
    for (int i = 0; i < NC; i++) {
        if (i + 1 < NC) asm volatile("cp.async.wait_group 1;");
        else            asm volatile("cp.async.wait_group 0;");
        __syncthreads();
        // prefetch stage i+2 into the buffer freed by iter i-1
        if (i + 2 < NC) {
            uint32_t stw = sb + (uint32_t)((i + 2) % NSTG) * STGSZ;
            load_stage<K, SPLIT3>(stw, tid, Ahi, Alo, Bhi, Blo, arow, brow, i + 2);
        }
        uint32_t st = sb + (uint32_t)(i % NSTG) * STGSZ;
        #pragma unroll
        for (int ks = 0; ks < 2; ks++) {
            uint32_t kb = (uint32_t)(ks * 32);
            uint32_t ah[2][4], al[2][4];
            #pragma unroll
            for (int mt = 0; mt < 2; mt++) {
                uint32_t a = st + a_off + (uint32_t)(mt * 16 * 80) + kb;
                ldsm4(a, ah[mt][0], ah[mt][1], ah[mt][2], ah[mt][3]);
                if (SPLIT3) ldsm4(a + A_SZ, al[mt][0], al[mt][1], al[mt][2], al[mt][3]);
            }
            #pragma unroll
            for (int np = 0; np < 8; np++) {
                uint32_t b = st + b_off + (uint32_t)(np * 16 * 80) + kb;
                uint32_t bh[4], bl[4];
                ldsm4(b, bh[0], bh[1], bh[2], bh[3]);
                if (SPLIT3) ldsm4(b + B_SZ, bl[0], bl[1], bl[2], bl[3]);
                #pragma unroll
                for (int mt = 0; mt < 2; mt++) {
                    #pragma unroll
                    for (int hh = 0; hh < 2; hh++) {
                        float* c = acc[mt][np * 2 + hh];
                        mma16816(c, ah[mt], bh[hh * 2], bh[hh * 2 + 1]);
                        if (SPLIT3) {
                            mma16816(c, ah[mt], bl[hh * 2], bl[hh * 2 + 1]);
                            mma16816(c, al[mt], bh[hh * 2], bh[hh * 2 + 1]);
                        }
                    }
                }
            }
        }
    }

    // ---- epilogue ----
    const int quad = lane >> 2, qi = lane & 3;
    #pragma unroll
    for (int mt = 0; mt < 2; mt++) {
        #pragma unroll
        for (int nt = 0; nt < 16; nt++) {
            int r0 = by * 128 + wm * 32 + mt * 16 + quad;
            int c  = bx * 256 + wn * 128 + nt * 8 + qi * 2;
            float* a = acc[mt][nt];
            #pragma unroll
            for (int half = 0; half < 2; half++) {
                int row = r0 + half * 8;
                float v0 = a[half * 2], v1 = a[half * 2 + 1];
                if (MODE == 0) {
                    float* dst = (c < DI) ? (g_u + (size_t)row * DI + c)
                                          : (g_z + (size_t)row * DI + (c - DI));
                    *(float2*)dst = make_float2(v0, v1);
                } else if (MODE == 1) {
                    float2 bb = *(const float2*)(p0 + c);
                    float2 o = make_float2(softplus_clamp(v0 + bb.x),
                                           softplus_clamp(v1 + bb.y));
                    *(float2*)(g_delta + (size_t)row * DI + c) = o;
                } else if (MODE == 2) {
                    size_t o = (size_t)row * DI + c;
                    float2 uu = *(const float2*)(g_uact + o);
                    float2 zz = *(const float2*)(g_z + o);
                    float2 dp = *(const float2*)(p0 + c);
                    float w0 = (v0 + uu.x * dp.x) * siluf(zz.x);
                    float w1 = (v1 + uu.y * dp.y) * siluf(zz.y);
                    __nv_bfloat16 h0, l0, h1, l1;
                    split2(w0, h0, l0);
                    split2(w1, h1, l1);
                    *(__nv_bfloat162*)(g_g_hi + o) = __nv_bfloat162(h0, h1);
                    *(__nv_bfloat162*)(g_g_lo + o) = __nv_bfloat162(l0, l1);
                } else {
                    size_t o = (size_t)row * (size_t)NOUT + c;
                    float2 rr = *(const float2*)(res + o);
                    *(float2*)(outp + o) = make_float2(v0 + rr.x, v1 + rr.y);
                }
            }
        }
    }
}

// ---------------- local depthwise conv (zero pad) + bias + SiLU ----------------
__global__ void __launch_bounds__(256) conv_local_kernel(const float* __restrict__ w,
                                                         const float* __restrict__ bias) {
    int idx = blockIdx.x * 256 + threadIdx.x;
    int c = idx & (DI - 1);
    int n = (idx >> 10) & 4095;
    int b = idx >> 22;
    int y = n >> 6, x = n & 63;
    const float* wc = w + c * 9;
    float acc = bias[c];
    #pragma unroll
    for (int ky = 0; ky < 3; ky++) {
        int yy = y + ky - 1;
        if ((unsigned)yy >= 64u) continue;
        #pragma unroll
        for (int kx = 0; kx < 3; kx++) {
            int xx = x + kx - 1;
            if ((unsigned)xx >= 64u) continue;
            int srow = (b << 12) | (yy << 6) | xx;
            acc = fmaf(wc[ky * 3 + kx], g_u[(size_t)srow * DI + c], acc);
        }
    }
    float v = siluf(acc);
    g_uact[idx] = v;
    __nv_bfloat16 hi, lo;
    split2(v, hi, lo);
    g_ua_hi[idx] = hi;
    g_ua_lo[idx] = lo;
}

// ---------------- diff conv (replicate pad) + Euler step ----------------
template<bool LAST>
__global__ void __launch_bounds__(256) conv_diff_kernel(const float* __restrict__ hin,
                                                        float* __restrict__ hout,
                                                        const float* __restrict__ w,
                                                        const float* __restrict__ alpha,
                                                        const float* __restrict__ beta) {
    int idx = blockIdx.x * 256 + threadIdx.x;
    int c = idx & (DI - 1);
    int n = (idx >> 10) & 4095;
    int b = idx >> 22;
    int y = n >> 6, x = n & 63;
    const float* wc = w + c * 9;
    float acc = 0.f;
    #pragma unroll
    for (int ky = 0; ky < 3; ky++) {
        int yy = min(max(y + ky - 1, 0), 63);
        #pragma unroll
        for (int kx = 0; kx < 3; kx++) {
            int xx = min(max(x + kx - 1, 0), 63);
            int srow = (b << 12) | (yy << 6) | xx;
            acc = fmaf(wc[ky * 3 + kx], hin[(size_t)srow * DI + c], acc);
        }
    }
    float h = hin[idx];
    float d = g_delta[idx];
    float v = h + 0.25f * (d * acc + alpha[c] * h - beta[c] * h * h * h);
    if (LAST) {
        __nv_bfloat16 hi, lo;
        split2(v, hi, lo);
        g_h_hi[idx] = hi;
        g_h_lo[idx] = lo;
    } else {
        hout[idx] = v;
    }
}

extern "C" void kernel_launch(void* const* d_in, const int* in_sizes, int n_in,
                              void* d_out, int out_size) {
    const float* x         = (const float*)d_in[0];
    const float* ln_gamma  = (const float*)d_in[1];
    const float* ln_beta   = (const float*)d_in[2];
    const float* W_in      = (const float*)d_in[3];
    const float* conv_lw   = (const float*)d_in[4];
    const float* conv_lb   = (const float*)d_in[5];
    const float* W_dt      = (const float*)d_in[6];
    const float* b_dt      = (const float*)d_in[7];
    const float* D_param   = (const float*)d_in[8];
    const float* conv_dw   = (const float*)d_in[9];
    const float* alpha     = (const float*)d_in[10];
    const float* beta_r    = (const float*)d_in[11];
    const float* W_ssm_out = (const float*)d_in[12];
    const float* W_out     = (const float*)d_in[13];
    float* out             = (float*)d_out;

    __nv_bfloat16 *xn_hi, *xn_lo, *ua_hi, *ua_lo, *h_hi, *h_lo, *gg_hi, *gg_lo;
    __nv_bfloat16 *win_hi, *win_lo, *wdt_hi, *wdt_lo, *wssm_hi, *wssm_lo, *wout_hi, *wout_lo;
    float *hA, *hB, *uact;
    cudaGetSymbolAddress((void**)&xn_hi, g_xn_hi);
    cudaGetSymbolAddress((void**)&xn_lo, g_xn_lo);
    cudaGetSymbolAddress((void**)&ua_hi, g_ua_hi);
    cudaGetSymbolAddress((void**)&ua_lo, g_ua_lo);
    cudaGetSymbolAddress((void**)&h_hi,  g_h_hi);
    cudaGetSymbolAddress((void**)&h_lo,  g_h_lo);
    cudaGetSymbolAddress((void**)&gg_hi, g_g_hi);
    cudaGetSymbolAddress((void**)&gg_lo, g_g_lo);
    cudaGetSymbolAddress((void**)&win_hi,  g_win_hi);
    cudaGetSymbolAddress((void**)&win_lo,  g_win_lo);
    cudaGetSymbolAddress((void**)&wdt_hi,  g_wdt_hi);
    cudaGetSymbolAddress((void**)&wdt_lo,  g_wdt_lo);
    cudaGetSymbolAddress((void**)&wssm_hi, g_wssm_hi);
    cudaGetSymbolAddress((void**)&wssm_lo, g_wssm_lo);
    cudaGetSymbolAddress((void**)&wout_hi, g_wout_hi);
    cudaGetSymbolAddress((void**)&wout_lo, g_wout_lo);
    cudaGetSymbolAddress((void**)&hA,   g_hA);
    cudaGetSymbolAddress((void**)&hB,   g_hB);
    cudaGetSymbolAddress((void**)&uact, g_uact);

    const int SMEM_BYTES = NSTG * STGSZ;  // 184320
    cudaFuncSetAttribute((const void*)hmma_gemm<0, 2048, 512,  true>,
                         cudaFuncAttributeMaxDynamicSharedMemorySize, SMEM_BYTES);
    cudaFuncSetAttribute((const void*)hmma_gemm<1, 1024, 1024, false>,
                         cudaFuncAttributeMaxDynamicSharedMemorySize, SMEM_BYTES);
    cudaFuncSetAttribute((const void*)hmma_gemm<2, 1024, 1024, true>,
                         cudaFuncAttributeMaxDynamicSharedMemorySize, SMEM_BYTES);
    cudaFuncSetAttribute((const void*)hmma_gemm<3, 512,  1024, true>,
                         cudaFuncAttributeMaxDynamicSharedMemorySize, SMEM_BYTES);

    const int EW_BLOCKS = (ROWS * DI) / 256;

    // 0) weight transpose + split
    wprep_kernel<<<dim3(2048 / 32, 512 / 32),  256>>>(W_in,      win_hi,  win_lo,  512,  2048);
    wprep_kernel<<<dim3(1024 / 32, 1024 / 32), 256>>>(W_dt,      wdt_hi,  wdt_lo,  1024, 1024);
    wprep_kernel<<<dim3(1024 / 32, 1024 / 32), 256>>>(W_ssm_out, wssm_hi, wssm_lo, 1024, 1024);
    wprep_kernel<<<dim3(512 / 32,  1024 / 32), 256>>>(W_out,     wout_hi, wout_lo, 1024, 512);

    // 1) LayerNorm -> xn hi/lo
    ln_kernel<<<ROWS, 256>>>(x, ln_gamma, ln_beta);

    // 2) in_proj -> u (g_u) and z (g_z)
    hmma_gemm<0, 2048, 512, true><<<dim3(8, ROWS / 128), 256, SMEM_BYTES>>>(
        xn_hi, xn_lo, win_hi, win_lo, nullptr, nullptr, nullptr);

    // 3) local conv + SiLU -> uact (fp32 + hi/lo)
    conv_local_kernel<<<EW_BLOCKS, 256>>>(conv_lw, conv_lb);

    // 4) delta (hi-only)
    hmma_gemm<1, 1024, 1024, false><<<dim3(4, ROWS / 128), 256, SMEM_BYTES>>>(
        ua_hi, ua_lo, wdt_hi, wdt_lo, b_dt, nullptr, nullptr);

    // 5) Euler x4 (last writes h hi/lo)
    conv_diff_kernel<false><<<EW_BLOCKS, 256>>>(uact, hA, conv_dw, alpha, beta_r);
    conv_diff_kernel<false><<<EW_BLOCKS, 256>>>(hA,   hB, conv_dw, alpha, beta_r);
    conv_diff_kernel<false><<<EW_BLOCKS, 256>>>(hB,   hA, conv_dw, alpha, beta_r);
    conv_diff_kernel<true ><<<EW_BLOCKS, 256>>>(hA, nullptr, conv_dw, alpha, beta_r);

    // 6) g = (h@Wssm + u*D) * silu(z) -> g hi/lo
    hmma_gemm<2, 1024, 1024, true><<<dim3(4, ROWS / 128), 256, SMEM_BYTES>>>(
        h_hi, h_lo, wssm_hi, wssm_lo, D_param, nullptr, nullptr);

    // 7) out = g@Wout + residual
    hmma_gemm<3, 512, 1024, true><<<dim3(2, ROWS / 128), 256, SMEM_BYTES>>>(
        gg_hi, gg_lo, wout_hi, wout_lo, nullptr, x, out);
}

// round 5
// speedup vs baseline: 2.6429x; 1.1891x over previous
#include <cuda_runtime.h>
#include <cuda_fp16.h>
#include <math.h>
#include <stdint.h>

#define D_MODEL 512
#define DI      1024
#define ROWS    32768

// ---------------- scratch (device globals) ----------------
__device__ __half g_xn_hi[ROWS * D_MODEL];
__device__ __half g_xn_lo[ROWS * D_MODEL];
__device__ float g_u    [ROWS * DI];
__device__ float g_z    [ROWS * DI];
__device__ float g_uact [ROWS * DI];
__device__ __half g_ua_hi[ROWS * DI];
__device__ float g_delta[ROWS * DI];
__device__ float g_hA   [ROWS * DI];
__device__ float g_hB   [ROWS * DI];
__device__ __half g_h_hi[ROWS * DI];
__device__ __half g_h_lo[ROWS * DI];
__device__ __half g_g_hi[ROWS * DI];
__device__ __half g_g_lo[ROWS * DI];
// transposed weights: [N][K] fp16 (hi only — B-side rounding error ~2^-12)
__device__ __half g_win_t [2048 * 512];
__device__ __half g_wdt_t [1024 * 1024];
__device__ __half g_wssm_t[1024 * 1024];
__device__ __half g_wout_t[512 * 1024];

// ---------------- small helpers ----------------
__device__ __forceinline__ float siluf(float v) { return v / (1.0f + expf(-v)); }
__device__ __forceinline__ float softplus_clamp(float v) {
    float sp = (v > 15.0f) ? v : log1pf(expf(v));
    return fminf(sp, 0.15f);
}
__device__ __forceinline__ void split2h(float v, __half& hi, __half& lo) {
    hi = __float2half_rn(v);
    lo = __float2half_rn(v - __half2float(hi));
}

__device__ __forceinline__ void cpasync16(uint32_t dst, const void* src) {
    asm volatile("cp.async.cg.shared.global [%0], [%1], 16;" :: "r"(dst), "l"(src));
}
__device__ __forceinline__ void ldsm4(uint32_t a, uint32_t& r0, uint32_t& r1,
                                      uint32_t& r2, uint32_t& r3) {
    asm volatile("ldmatrix.sync.aligned.m8n8.x4.shared.b16 {%0,%1,%2,%3}, [%4];"
                 : "=r"(r0), "=r"(r1), "=r"(r2), "=r"(r3) : "r"(a));
}
__device__ __forceinline__ void mma16816h(float* c, const uint32_t* a,
                                          uint32_t b0, uint32_t b1) {
    asm volatile(
        "mma.sync.aligned.m16n8k16.row.col.f32.f16.f16.f32 "
        "{%0,%1,%2,%3}, {%4,%5,%6,%7}, {%8,%9}, {%0,%1,%2,%3};"
        : "+f"(c[0]), "+f"(c[1]), "+f"(c[2]), "+f"(c[3])
        : "r"(a[0]), "r"(a[1]), "r"(a[2]), "r"(a[3]), "r"(b0), "r"(b1));
}

// ---------------- LayerNorm -> fp16 hi/lo split ----------------
__global__ void __launch_bounds__(256) ln_kernel(const float* __restrict__ x,
                                                 const float* __restrict__ gamma,
                                                 const float* __restrict__ beta) {
    int row = blockIdx.x;
    const float* xr = x + (size_t)row * D_MODEL;
    int t = threadIdx.x;
    float v0 = xr[t], v1 = xr[t + 256];
    float s = v0 + v1, sq = v0 * v0 + v1 * v1;
    __shared__ float sh[32], shq[32];
    #pragma unroll
    for (int o = 16; o; o >>= 1) {
        s  += __shfl_down_sync(0xffffffffu, s,  o);
        sq += __shfl_down_sync(0xffffffffu, sq, o);
    }
    int lane = t & 31, w = t >> 5;
    if (lane == 0) { sh[w] = s; shq[w] = sq; }
    __syncthreads();
    if (t == 0) {
        float ts = 0.f, tq = 0.f;
        #pragma unroll
        for (int i = 0; i < 8; i++) { ts += sh[i]; tq += shq[i]; }
        float mu = ts * (1.0f / D_MODEL);
        float var = tq * (1.0f / D_MODEL) - mu * mu;
        sh[0] = mu;
        shq[0] = rsqrtf(var + 1e-5f);
    }
    __syncthreads();
    float mu = sh[0], rs = shq[0];
    size_t o = (size_t)row * D_MODEL;
    float a = (v0 - mu) * rs * gamma[t] + beta[t];
    float b = (v1 - mu) * rs * gamma[t + 256] + beta[t + 256];
    __half hi, lo;
    split2h(a, hi, lo); g_xn_hi[o + t] = hi;       g_xn_lo[o + t] = lo;
    split2h(b, hi, lo); g_xn_hi[o + t + 256] = hi; g_xn_lo[o + t + 256] = lo;
}

// ---------------- weight transpose (fp16), two matrices per launch ----------------
__device__ __forceinline__ void wprep_tile(const float* __restrict__ W,
                                           __half* __restrict__ T,
                                           int K, int N, int tile) {
    __shared__ float t[32][33];
    int ntiles = N >> 5;
    int n0 = (tile % ntiles) * 32, k0 = (tile / ntiles) * 32;
    int tx = threadIdx.x & 31, ty = threadIdx.x >> 5;
    #pragma unroll
    for (int dy = 0; dy < 32; dy += 8)
        t[ty + dy][tx] = W[(size_t)(k0 + ty + dy) * N + n0 + tx];
    __syncthreads();
    #pragma unroll
    for (int dy = 0; dy < 32; dy += 8)
        T[(size_t)(n0 + ty + dy) * K + k0 + tx] = __float2half_rn(t[tx][ty + dy]);
}

__global__ void __launch_bounds__(256) wprep2_kernel(
        const float* __restrict__ W0, __half* __restrict__ T0, int K0, int N0, int ntile0,
        const float* __restrict__ W1, __half* __restrict__ T1, int K1, int N1) {
    int b = blockIdx.x;
    if (b < ntile0) wprep_tile(W0, T0, K0, N0, b);
    else            wprep_tile(W1, T1, K1, N1, b - ntile0);
}

// ---------------- HMMA fp16 2-product GEMM, 128x256x32 tiles, 3-stage ----------------
// smem per stage: Ahi(10240) Alo(10240) B(20480) = 40960 B
#define A_SZ   10240u
#define B_OFF  20480u
#define STGSZ  40960u
#define NSTG   3

template<int K, int NPROD>
__device__ __forceinline__ void load_stage(uint32_t st, int tid,
        const __half* __restrict__ Ahi, const __half* __restrict__ Alo,
        const __half* __restrict__ B,
        size_t arow, size_t brow, int chunk) {
    #pragma unroll
    for (int i = 0; i < 2; i++) {
        int idx = tid + i * 256;
        int r = idx >> 2, cb = (idx & 3) * 16;
        uint32_t sa = st + (uint32_t)(r * 80 + cb);
        size_t ga = (arow + r) * (size_t)(K * 2) + chunk * 64 + cb;
        cpasync16(sa, (const char*)Ahi + ga);
        if (NPROD == 2) cpasync16(sa + A_SZ, (const char*)Alo + ga);
    }
    #pragma unroll
    for (int i = 0; i < 4; i++) {
        int idx = tid + i * 256;
        int r = idx >> 2, cb = (idx & 3) * 16;
        uint32_t sbm = st + B_OFF + (uint32_t)(r * 80 + cb);
        size_t gb = (brow + r) * (size_t)(K * 2) + chunk * 64 + cb;
        cpasync16(sbm, (const char*)B + gb);
    }
    asm volatile("cp.async.commit_group;");
}

template<int MODE, int NOUT, int K, int NPROD>
__global__ void __launch_bounds__(256, 1)
hmma_gemm(const __half* __restrict__ Ahi, const __half* __restrict__ Alo,
          const __half* __restrict__ B,
          const float* __restrict__ p0, const float* __restrict__ res,
          float* __restrict__ outp) {
    extern __shared__ char smem_raw[];
    uint32_t sb = (uint32_t)__cvta_generic_to_shared(smem_raw);
    const int tid = threadIdx.x;
    const int lane = tid & 31, wid = tid >> 5;
    const int wm = wid & 3, wn = wid >> 2;           // 4m x 2n, warp tile 32x128
    const int bx = blockIdx.x, by = blockIdx.y;
    const size_t arow = (size_t)by * 128;
    const size_t brow = (size_t)bx * 256;
    constexpr int NC = K / 32;

    const int a_r = (lane & 7) + ((lane >> 3) & 1) * 8;
    const int a_c = ((lane >> 4) & 1) * 8;
    const int b_r = (lane & 7) + ((lane >> 4) & 1) * 8;
    const int b_c = ((lane >> 3) & 1) * 8;
    const uint32_t a_off = (uint32_t)((wm * 32 + a_r) * 80 + a_c * 2);
    const uint32_t b_off = B_OFF + (uint32_t)((wn * 128 + b_r) * 80 + b_c * 2);

    load_stage<K, NPROD>(sb,         tid, Ahi, Alo, B, arow, brow, 0);
    load_stage<K, NPROD>(sb + STGSZ, tid, Ahi, Alo, B, arow, brow, 1);

    float acc[2][16][4];
    #pragma unroll
    for (int i = 0; i < 2; i++)
        #pragma unroll
        for (int j = 0; j < 16; j++)
            #pragma unroll
            for (int q = 0; q < 4; q++) acc[i][j][q] = 0.f;

    #pragma unroll 1
    for (int i = 0; i < NC; i++) {
        if (i + 1 < NC) asm volatile("cp.async.wait_group 1;");
        else            asm volatile("cp.async.wait_group 0;");
        __syncthreads();
        if (i + 2 < NC) {
            uint32_t stw = sb + (uint32_t)((i + 2) % NSTG) * STGSZ;
            load_stage<K, NPROD>(stw, tid, Ahi, Alo, B, arow, brow, i + 2);
        }
        uint32_t st = sb + (uint32_t)(i % NSTG) * STGSZ;
        #pragma unroll
        for (int ks = 0; ks < 2; ks++) {
            uint32_t kb = (uint32_t)(ks * 32);
            uint32_t ah[2][4], al[2][4];
            #pragma unroll
            for (int mt = 0; mt < 2; mt++) {
                uint32_t a = st + a_off + (uint32_t)(mt * 16 * 80) + kb;
                ldsm4(a, ah[mt][0], ah[mt][1], ah[mt][2], ah[mt][3]);
                if (NPROD == 2) ldsm4(a + A_SZ, al[mt][0], al[mt][1], al[mt][2], al[mt][3]);
            }
            #pragma unroll
            for (int np = 0; np < 8; np++) {
                uint32_t b = st + b_off + (uint32_t)(np * 16 * 80) + kb;
                uint32_t bh[4];
                ldsm4(b, bh[0], bh[1], bh[2], bh[3]);
                #pragma unroll
                for (int mt = 0; mt < 2; mt++) {
                    #pragma unroll
                    for (int hh = 0; hh < 2; hh++) {
                        float* c = acc[mt][np * 2 + hh];
                        mma16816h(c, ah[mt], bh[hh * 2], bh[hh * 2 + 1]);
                        if (NPROD == 2)
                            mma16816h(c, al[mt], bh[hh * 2], bh[hh * 2 + 1]);
                    }
                }
            }
        }
    }

    // ---- epilogue ----
    const int quad = lane >> 2, qi = lane & 3;
    #pragma unroll
    for (int mt = 0; mt < 2; mt++) {
        #pragma unroll
        for (int nt = 0; nt < 16; nt++) {
            int r0 = by * 128 + wm * 32 + mt * 16 + quad;
            int c  = bx * 256 + wn * 128 + nt * 8 + qi * 2;
            float* a = acc[mt][nt];
            #pragma unroll
            for (int half = 0; half < 2; half++) {
                int row = r0 + half * 8;
                float v0 = a[half * 2], v1 = a[half * 2 + 1];
                if (MODE == 0) {
                    float* dst = (c < DI) ? (g_u + (size_t)row * DI + c)
                                          : (g_z + (size_t)row * DI + (c - DI));
                    *(float2*)dst = make_float2(v0, v1);
                } else if (MODE == 1) {
                    float2 bb = *(const float2*)(p0 + c);
                    float2 o = make_float2(softplus_clamp(v0 + bb.x),
                                           softplus_clamp(v1 + bb.y));
                    *(float2*)(g_delta + (size_t)row * DI + c) = o;
                } else if (MODE == 2) {
                    size_t o = (size_t)row * DI + c;
                    float2 uu = *(const float2*)(g_uact + o);
                    float2 zz = *(const float2*)(g_z + o);
                    float2 dp = *(const float2*)(p0 + c);
                    float w0 = (v0 + uu.x * dp.x) * siluf(zz.x);
                    float w1 = (v1 + uu.y * dp.y) * siluf(zz.y);
                    __half h0, l0, h1, l1;
                    split2h(w0, h0, l0);
                    split2h(w1, h1, l1);
                    *(__half2*)(g_g_hi + o) = __half2(h0, h1);
                    *(__half2*)(g_g_lo + o) = __half2(l0, l1);
                } else {
                    size_t o = (size_t)row * (size_t)NOUT + c;
                    float2 rr = *(const float2*)(res + o);
                    *(float2*)(outp + o) = make_float2(v0 + rr.x, v1 + rr.y);
                }
            }
        }
    }
}

// ---------------- local depthwise conv (zero pad) + bias + SiLU ----------------
__global__ void __launch_bounds__(256) conv_local_kernel(const float* __restrict__ w,
                                                         const float* __restrict__ bias) {
    int idx = blockIdx.x * 256 + threadIdx.x;
    int c = idx & (DI - 1);
    int n = (idx >> 10) & 4095;
    int b = idx >> 22;
    int y = n >> 6, x = n & 63;
    const float* wc = w + c * 9;
    float acc = bias[c];
    #pragma unroll
    for (int ky = 0; ky < 3; ky++) {
        int yy = y + ky - 1;
        if ((unsigned)yy >= 64u) continue;
        #pragma unroll
        for (int kx = 0; kx < 3; kx++) {
            int xx = x + kx - 1;
            if ((unsigned)xx >= 64u) continue;
            int srow = (b << 12) | (yy << 6) | xx;
            acc = fmaf(wc[ky * 3 + kx], g_u[(size_t)srow * DI + c], acc);
        }
    }
    float v = siluf(acc);
    g_uact[idx] = v;
    g_ua_hi[idx] = __float2half_rn(v);
}

// ---------------- diff conv (replicate pad) + Euler step ----------------
template<bool LAST>
__global__ void __launch_bounds__(256) conv_diff_kernel(const float* __restrict__ hin,
                                                        float* __restrict__ hout,
                                                        const float* __restrict__ w,
                                                        const float* __restrict__ alpha,
                                                        const float* __restrict__ beta) {
    int idx = blockIdx.x * 256 + threadIdx.x;
    int c = idx & (DI - 1);
    int n = (idx >> 10) & 4095;
    int b = idx >> 22;
    int y = n >> 6, x = n & 63;
    const float* wc = w + c * 9;
    float acc = 0.f;
    #pragma unroll
    for (int ky = 0; ky < 3; ky++) {
        int yy = min(max(y + ky - 1, 0), 63);
        #pragma unroll
        for (int kx = 0; kx < 3; kx++) {
            int xx = min(max(x + kx - 1, 0), 63);
            int srow = (b << 12) | (yy << 6) | xx;
            acc = fmaf(wc[ky * 3 + kx], hin[(size_t)srow * DI + c], acc);
        }
    }
    float h = hin[idx];
    float d = g_delta[idx];
    float v = h + 0.25f * (d * acc + alpha[c] * h - beta[c] * h * h * h);
    if (LAST) {
        __half hi, lo;
        split2h(v, hi, lo);
        g_h_hi[idx] = hi;
        g_h_lo[idx] = lo;
    } else {
        hout[idx] = v;
    }
}

extern "C" void kernel_launch(void* const* d_in, const int* in_sizes, int n_in,
                              void* d_out, int out_size) {
    const float* x         = (const float*)d_in[0];
    const float* ln_gamma  = (const float*)d_in[1];
    const float* ln_beta   = (const float*)d_in[2];
    const float* W_in      = (const float*)d_in[3];
    const float* conv_lw   = (const float*)d_in[4];
    const float* conv_lb   = (const float*)d_in[5];
    const float* W_dt      = (const float*)d_in[6];
    const float* b_dt      = (const float*)d_in[7];
    const float* D_param   = (const float*)d_in[8];
    const float* conv_dw   = (const float*)d_in[9];
    const float* alpha     = (const float*)d_in[10];
    const float* beta_r    = (const float*)d_in[11];
    const float* W_ssm_out = (const float*)d_in[12];
    const float* W_out     = (const float*)d_in[13];
    float* out             = (float*)d_out;

    __half *xn_hi, *xn_lo, *ua_hi, *h_hi, *h_lo, *gg_hi, *gg_lo;
    __half *win_t, *wdt_t, *wssm_t, *wout_t;
    float *hA, *hB, *uact;
    cudaGetSymbolAddress((void**)&xn_hi, g_xn_hi);
    cudaGetSymbolAddress((void**)&xn_lo, g_xn_lo);
    cudaGetSymbolAddress((void**)&ua_hi, g_ua_hi);
    cudaGetSymbolAddress((void**)&h_hi,  g_h_hi);
    cudaGetSymbolAddress((void**)&h_lo,  g_h_lo);
    cudaGetSymbolAddress((void**)&gg_hi, g_g_hi);
    cudaGetSymbolAddress((void**)&gg_lo, g_g_lo);
    cudaGetSymbolAddress((void**)&win_t,  g_win_t);
    cudaGetSymbolAddress((void**)&wdt_t,  g_wdt_t);
    cudaGetSymbolAddress((void**)&wssm_t, g_wssm_t);
    cudaGetSymbolAddress((void**)&wout_t, g_wout_t);
    cudaGetSymbolAddress((void**)&hA,   g_hA);
    cudaGetSymbolAddress((void**)&hB,   g_hB);
    cudaGetSymbolAddress((void**)&uact, g_uact);

    const int SMEM_BYTES = NSTG * STGSZ;  // 122880
    cudaFuncSetAttribute((const void*)hmma_gemm<0, 2048, 512,  2>,
                         cudaFuncAttributeMaxDynamicSharedMemorySize, SMEM_BYTES);
    cudaFuncSetAttribute((const void*)hmma_gemm<1, 1024, 1024, 1>,
                         cudaFuncAttributeMaxDynamicSharedMemorySize, SMEM_BYTES);
    cudaFuncSetAttribute((const void*)hmma_gemm<2, 1024, 1024, 2>,
                         cudaFuncAttributeMaxDynamicSharedMemorySize, SMEM_BYTES);
    cudaFuncSetAttribute((const void*)hmma_gemm<3, 512,  1024, 2>,
                         cudaFuncAttributeMaxDynamicSharedMemorySize, SMEM_BYTES);

    const int EW_BLOCKS = (ROWS * DI) / 256;

    // 0) weight transpose to fp16 (2 launches; W_in+W_dt = 1024+1024 tiles,
    //    W_ssm+W_out = 1024+512 tiles)
    wprep2_kernel<<<2048, 256>>>(W_in, win_t, 512, 2048, 1024,
                                 W_dt, wdt_t, 1024, 1024);
    wprep2_kernel<<<1536, 256>>>(W_ssm_out, wssm_t, 1024, 1024, 1024,
                                 W_out, wout_t, 1024, 512);

    // 1) LayerNorm -> xn hi/lo
    ln_kernel<<<ROWS, 256>>>(x, ln_gamma, ln_beta);

    // 2) in_proj -> u (g_u) and z (g_z)
    hmma_gemm<0, 2048, 512, 2><<<dim3(8, ROWS / 128), 256, SMEM_BYTES>>>(
        xn_hi, xn_lo, win_t, nullptr, nullptr, nullptr);

    // 3) local conv + SiLU -> uact (fp32 + fp16 hi)
    conv_local_kernel<<<EW_BLOCKS, 256>>>(conv_lw, conv_lb);

    // 4) delta (1-product fp16)
    hmma_gemm<1, 1024, 1024, 1><<<dim3(4, ROWS / 128), 256, SMEM_BYTES>>>(
        ua_hi, ua_hi, wdt_t, b_dt, nullptr, nullptr);

    // 5) Euler x4 (last writes h hi/lo)
    conv_diff_kernel<false><<<EW_BLOCKS, 256>>>(uact, hA, conv_dw, alpha, beta_r);
    conv_diff_kernel<false><<<EW_BLOCKS, 256>>>(hA,   hB, conv_dw, alpha, beta_r);
    conv_diff_kernel<false><<<EW_BLOCKS, 256>>>(hB,   hA, conv_dw, alpha, beta_r);
    conv_diff_kernel<true ><<<EW_BLOCKS, 256>>>(hA, nullptr, conv_dw, alpha, beta_r);

    // 6) g = (h@Wssm + u*D) * silu(z) -> g hi/lo
    hmma_gemm<2, 1024, 1024, 2><<<dim3(4, ROWS / 128), 256, SMEM_BYTES>>>(
        h_hi, h_lo, wssm_t, D_param, nullptr, nullptr);

    // 7) out = g@Wout + residual
    hmma_gemm<3, 512, 1024, 2><<<dim3(2, ROWS / 128), 256, SMEM_BYTES>>>(
        gg_hi, gg_lo, wout_t, nullptr, x, out);
}